// round 14
// baseline (speedup 1.0000x reference)
#include <cuda_runtime.h>
#include <cstdint>

#define HEADS 16
#define DIMD 128
#define NSEQ 2048
/* exp(x*INV_SQRT_N) == exp2(x*C2) */
#define C2 0.0318793576f
#define KSPLIT 8

// ---------------- scratch (static device globals; no allocations) ----------------
__device__ __align__(16) uint32_t g_qp2[HEADS * NSEQ * 64];   // f16x2 packed
__device__ __align__(16) uint32_t g_kp2[HEADS * NSEQ * 64];   // f16x2 packed
__device__ __align__(16) uint32_t g_vp2[HEADS * NSEQ * 64];   // f16x2 packed
__device__ __align__(16) uint32_t g_ctx2[NSEQ * 1024];        // f16x2 packed [n][h*64+du]
__device__ __align__(16) float g_part[KSPLIT * NSEQ * DIMD];
__device__ __align__(16) unsigned g_mbits[(NSEQ / 32) * NSEQ];  // [word][row]

// ---------------- helpers ----------------
__device__ __forceinline__ uint32_t f2h2(float lo, float hi) {
  uint32_t r;
  asm("cvt.rn.f16x2.f32 %0, %1, %2;" : "=r"(r) : "f"(hi), "f"(lo));
  return r;
}
__device__ __forceinline__ uint32_t smem_u32(const void* p) {
  uint32_t a;
  asm("{ .reg .u64 t; cvta.to.shared.u64 t, %1; cvt.u32.u64 %0, t; }" : "=r"(a) : "l"(p));
  return a;
}

#define CP_ASYNC16(saddr, gptr)                                                 \
  asm volatile("cp.async.cg.shared.global [%0], [%1], 16;" ::"r"(saddr),        \
               "l"(gptr) : "memory")
#define CP_COMMIT() asm volatile("cp.async.commit_group;" ::: "memory")
#define CP_WAIT0() asm volatile("cp.async.wait_group 0;" ::: "memory")

__device__ __forceinline__ void mma_f16(float c[4], const uint32_t a[4],
                                        uint32_t b0, uint32_t b1) {
  asm volatile(
      "mma.sync.aligned.m16n8k16.row.col.f32.f16.f16.f32 "
      "{%0,%1,%2,%3}, {%4,%5,%6,%7}, {%8,%9}, {%0,%1,%2,%3};"
      : "+f"(c[0]), "+f"(c[1]), "+f"(c[2]), "+f"(c[3])
      : "r"(a[0]), "r"(a[1]), "r"(a[2]), "r"(a[3]), "r"(b0), "r"(b1));
}

__device__ __forceinline__ void ldmatrix_x4_trans(uint32_t& r0, uint32_t& r1,
                                                  uint32_t& r2, uint32_t& r3,
                                                  uint32_t addr) {
  asm volatile(
      "ldmatrix.sync.aligned.m8n8.x4.trans.shared.b16 {%0,%1,%2,%3}, [%4];"
      : "=r"(r0), "=r"(r1), "=r"(r2), "=r"(r3)
      : "r"(addr));
}

// ======================= kernel 1: projections (f16) + mask pack (z=3) ======
#define GW 68
__global__ void __launch_bounds__(256) proj_tc_kernel(
    const float* __restrict__ q, const float* __restrict__ k,
    const float* __restrict__ v, const float* __restrict__ Qw,
    const float* __restrict__ Kw, const float* __restrict__ Vw,
    const int* __restrict__ mask) {
  const int which = blockIdx.z;
  const int tid = threadIdx.x;
  const int wid = tid >> 5;
  const int lane = tid & 31;

  if (which == 3) {
    const int blkid = blockIdx.y * 16 + blockIdx.x;
    int wbase = blkid * 512 + wid * 64;
#pragma unroll 4
    for (int i = 0; i < 64; i++) {
      int w = wbase + i;
      int m = mask[(size_t)w * 32 + lane];
      unsigned bits = __ballot_sync(0xffffffffu, m != 0);
      if (lane == 0) g_mbits[(size_t)(w & 63) * NSEQ + (w >> 6)] = bits;
    }
    return;
  }

  extern __shared__ uint32_t smg[];
  uint32_t* Xs = smg;
  uint32_t* Ws = smg + 128 * GW;

  const float* A = (which == 0) ? q : (which == 1) ? k : v;
  const float* W = (which == 0) ? Qw : (which == 1) ? Kw : Vw;
  const int h = blockIdx.y;
  const int n0 = blockIdx.x * 128;
  const int qr = lane >> 2, qc = lane & 3;
  const int wm = (wid & 3) * 32;
  const int wn = (wid >> 2) * 64;

  for (int idx = tid; idx < 128 * 32; idx += 256) {
    int r = idx >> 5, c4 = (idx & 31) << 2;
    float4 t = *reinterpret_cast<const float4*>(A + (size_t)(n0 + r) * DIMD + c4);
    *reinterpret_cast<uint2*>(Xs + r * GW + (c4 >> 1)) =
        make_uint2(f2h2(t.x, t.y), f2h2(t.z, t.w));
  }
  const float* Wh = W + (size_t)h * DIMD * DIMD;
  for (int idx = tid; idx < 128 * 32; idx += 256) {
    int e = idx & 127, d4 = (idx >> 7) << 2;
    *reinterpret_cast<uint2*>(Ws + e * GW + (d4 >> 1)) = make_uint2(
        f2h2(Wh[(size_t)(d4 + 0) * DIMD + e], Wh[(size_t)(d4 + 1) * DIMD + e]),
        f2h2(Wh[(size_t)(d4 + 2) * DIMD + e], Wh[(size_t)(d4 + 3) * DIMD + e]));
  }
  __syncthreads();

  float O[2][8][4];
#pragma unroll
  for (int mt = 0; mt < 2; mt++)
#pragma unroll
    for (int nt = 0; nt < 8; nt++)
#pragma unroll
      for (int e = 0; e < 4; e++) O[mt][nt][e] = 0.f;

#pragma unroll
  for (int ks = 0; ks < 8; ks++) {
    const int k8 = ks * 8;
    uint32_t Af[2][4];
#pragma unroll
    for (int mt = 0; mt < 2; mt++) {
      const uint32_t* ab = Xs + (wm + mt * 16 + qr) * GW + k8 + qc;
      Af[mt][0] = ab[0];
      Af[mt][1] = ab[8 * GW];
      Af[mt][2] = ab[4];
      Af[mt][3] = ab[8 * GW + 4];
    }
#pragma unroll
    for (int nt = 0; nt < 8; nt++) {
      const uint32_t* bb = Ws + (wn + nt * 8 + qr) * GW + k8 + qc;
      uint32_t b0 = bb[0], b1 = bb[4];
      mma_f16(O[0][nt], Af[0], b0, b1);
      mma_f16(O[1][nt], Af[1], b0, b1);
    }
  }

  uint32_t* Cb2 = (which == 0 ? g_qp2 : which == 1 ? g_kp2 : g_vp2) +
                  ((size_t)h * NSEQ + n0) * 64;
#pragma unroll
  for (int mt = 0; mt < 2; mt++) {
#pragma unroll
    for (int nt = 0; nt < 8; nt++) {
      const int row0 = wm + mt * 16 + qr;
      const int cu = (wn + nt * 8) / 2 + qc;
      const float* o = O[mt][nt];
      Cb2[(size_t)row0 * 64 + cu] = f2h2(o[0], o[1]);
      Cb2[(size_t)(row0 + 8) * 64 + cu] = f2h2(o[2], o[3]);
    }
  }
}

// ======================= kernel 2: attention BM=128, 106.5KB smem, 2/SM ======
// 256 blocks, 512 threads / 16 warps, 4m x 4n. Single-buffered tiles filled by
// cp.async; P overlays Q. Cross-block co-residency hides phase latency.
#define ATW 68
#define AT_Q 8704
#define AT_V 17408
#define AT_L 26112
#define ATTN_SMEM_BYTES ((26112 + 512) * 4)

__global__ void __launch_bounds__(512, 2) attn_mma_kernel() {
  extern __shared__ uint32_t smu[];
  const uint32_t sbase = smem_u32(smu);
  uint32_t* Ks2 = smu;
  uint32_t* Ps2 = smu + AT_Q;  // P overlays Q
  float* l_sh = reinterpret_cast<float*>(smu + AT_L);

  const int tid = threadIdx.x;
  const int wid = tid >> 5;
  const int lane = tid & 31;
  const int qr = lane >> 2;
  const int qc = lane & 3;
  const int wm = (wid & 3) * 32;
  const int wn = (wid >> 2) * 32;

  const int h = blockIdx.y;
  const int i0 = blockIdx.x * 128;

  const uint32_t* kp2 = g_kp2 + (size_t)h * NSEQ * 64;
  const uint32_t* qp2 = g_qp2 + (size_t)h * NSEQ * 64;
  const uint32_t* vp2 = g_vp2 + (size_t)h * NSEQ * 64;

  const int cr = tid >> 4;
  const int cc4 = (tid & 15) << 2;
  const uint32_t so = (uint32_t)(cr * ATW + cc4) * 4u;

  // K tile via cp.async (completes at first wait0)
#pragma unroll
  for (int p = 0; p < 4; p++) {
    uint32_t o = so + (uint32_t)(p * 32 * ATW) * 4u;
    CP_ASYNC16(sbase + o, kp2 + (size_t)(i0 + cr + p * 32) * 64 + cc4);
  }

  const int lg = lane >> 3;
  const int vrow0 = (lane & 7) + ((lg & 1) << 3);
  const int vn0 = (wn >> 1) + ((lg >> 1) << 2);

  float O[2][4][4];
#pragma unroll
  for (int mt = 0; mt < 2; mt++)
#pragma unroll
    for (int nt = 0; nt < 4; nt++)
#pragma unroll
      for (int e = 0; e < 4; e++) O[mt][nt][e] = 0.f;
  float L[4] = {0.f, 0.f, 0.f, 0.f};

  const int row_rel[4] = {qr, qr + 8, qr + 16, qr + 24};

  for (int jt = 0; jt < NSEQ / 128; jt++) {
    const int j0 = jt * 128;
    __syncthreads();  // (A) prev PV done -> Q(P)/V buffers free

    // cp.async current tile Q, V
#pragma unroll
    for (int p = 0; p < 4; p++) {
      uint32_t o = so + (uint32_t)(p * 32 * ATW) * 4u;
      int r = j0 + cr + p * 32;
      CP_ASYNC16(sbase + AT_Q * 4u + o, qp2 + (size_t)r * 64 + cc4);
      CP_ASYNC16(sbase + AT_V * 4u + o, vp2 + (size_t)r * 64 + cc4);
    }
    CP_COMMIT();
    CP_WAIT0();
    __syncthreads();  // (B) tile resident

    const uint32_t* Qs2 = smu + AT_Q;
    const uint32_t vbase = sbase + AT_V * 4u;

    // ---- S = K · Q^T
    float S[2][4][4];
#pragma unroll
    for (int mt = 0; mt < 2; mt++)
#pragma unroll
      for (int nt = 0; nt < 4; nt++)
#pragma unroll
        for (int e = 0; e < 4; e++) S[mt][nt][e] = 0.f;

#pragma unroll
    for (int ks = 0; ks < 8; ks++) {
      const int k8 = ks * 8;
      uint32_t A[2][4];
#pragma unroll
      for (int mt = 0; mt < 2; mt++) {
        const uint32_t* ab = Ks2 + (wm + mt * 16 + qr) * ATW + k8 + qc;
        A[mt][0] = ab[0];
        A[mt][1] = ab[8 * ATW];
        A[mt][2] = ab[4];
        A[mt][3] = ab[8 * ATW + 4];
      }
#pragma unroll
      for (int nt = 0; nt < 4; nt++) {
        const uint32_t* bb = Qs2 + (wn + nt * 8 + qr) * ATW + k8 + qc;
        uint32_t b0 = bb[0], b1 = bb[4];
        mma_f16(S[0][nt], A[0], b0, b1);
        mma_f16(S[1][nt], A[1], b0, b1);
      }
    }

    // ---- masked exp
    const unsigned* mb = g_mbits + (size_t)((j0 + wn) >> 5) * NSEQ + i0 + wm;
    unsigned mw[4];
#pragma unroll
    for (int r = 0; r < 4; r++) mw[r] = mb[row_rel[r]];

    float lacc[4] = {0.f, 0.f, 0.f, 0.f};
#pragma unroll
    for (int mt = 0; mt < 2; mt++) {
#pragma unroll
      for (int nt = 0; nt < 4; nt++) {
        const int b0 = nt * 8 + 2 * qc;
        const unsigned w0 = mw[mt * 2], w1 = mw[mt * 2 + 1];
        float* s = S[mt][nt];
        float p0 = ((w0 >> b0) & 1u) ? exp2f(s[0] * C2) : 0.f;
        float p1 = ((w0 >> (b0 + 1)) & 1u) ? exp2f(s[1] * C2) : 0.f;
        float p2 = ((w1 >> b0) & 1u) ? exp2f(s[2] * C2) : 0.f;
        float p3 = ((w1 >> (b0 + 1)) & 1u) ? exp2f(s[3] * C2) : 0.f;
        s[0] = p0; s[1] = p1; s[2] = p2; s[3] = p3;
        lacc[mt * 2] += p0 + p1;
        lacc[mt * 2 + 1] += p2 + p3;
      }
    }
#pragma unroll
    for (int r = 0; r < 4; r++) {
      float v = lacc[r];
      v += __shfl_xor_sync(0xffffffffu, v, 1);
      v += __shfl_xor_sync(0xffffffffu, v, 2);
      L[r] += v;
    }

    __syncthreads();  // (C) all warps done reading Q -> overwrite with P

#pragma unroll
    for (int mt = 0; mt < 2; mt++) {
#pragma unroll
      for (int nt = 0; nt < 4; nt++) {
        const int row0 = wm + mt * 16 + qr;
        const int cu = (wn >> 1) + nt * 4 + qc;
        const float* s = S[mt][nt];
        Ps2[row0 * ATW + cu] = f2h2(s[0], s[1]);
        Ps2[(row0 + 8) * ATW + cu] = f2h2(s[2], s[3]);
      }
    }
    __syncthreads();  // (D) P complete

    // ---- O += P · V
    uint32_t vaddr0 = vbase + (uint32_t)(vrow0 * ATW + vn0) * 4u;
    uint32_t vaddr1 = vaddr0 + 32u;
#pragma unroll
    for (int ks = 0; ks < 8; ks++) {
      const int k8 = ks * 8;
      uint32_t A[2][4];
#pragma unroll
      for (int mt = 0; mt < 2; mt++) {
        const uint32_t* ab = Ps2 + (wm + mt * 16 + qr) * ATW + k8 + qc;
        A[mt][0] = ab[0];
        A[mt][1] = ab[8 * ATW];
        A[mt][2] = ab[4];
        A[mt][3] = ab[8 * ATW + 4];
      }
      uint32_t b0, b1, b2, b3;
      ldmatrix_x4_trans(b0, b1, b2, b3, vaddr0);
      mma_f16(O[0][0], A[0], b0, b1);
      mma_f16(O[1][0], A[1], b0, b1);
      mma_f16(O[0][1], A[0], b2, b3);
      mma_f16(O[1][1], A[1], b2, b3);
      ldmatrix_x4_trans(b0, b1, b2, b3, vaddr1);
      mma_f16(O[0][2], A[0], b0, b1);
      mma_f16(O[1][2], A[1], b0, b1);
      mma_f16(O[0][3], A[0], b2, b3);
      mma_f16(O[1][3], A[1], b2, b3);
      vaddr0 += 16u * ATW * 4u;
      vaddr1 += 16u * ATW * 4u;
    }
  }

  // combine row sums
  if (qc == 0) {
#pragma unroll
    for (int r = 0; r < 4; r++)
      l_sh[(wid >> 2) * 128 + wm + row_rel[r]] = L[r];
  }
  __syncthreads();
  float linv[4];
#pragma unroll
  for (int r = 0; r < 4; r++) {
    int row = wm + row_rel[r];
    linv[r] = 1.f / (l_sh[row] + l_sh[128 + row] + l_sh[256 + row] + l_sh[384 + row]);
  }

  // epilogue: write ctx as packed f16x2
#pragma unroll
  for (int mt = 0; mt < 2; mt++) {
#pragma unroll
    for (int nt = 0; nt < 4; nt++) {
      const int row0 = wm + mt * 16 + qr;
      const int cu = h * 64 + (wn >> 1) + nt * 4 + qc;
      const float* o = O[mt][nt];
      g_ctx2[(size_t)(i0 + row0) * 1024 + cu] =
          f2h2(o[0] * linv[mt * 2], o[1] * linv[mt * 2]);
      g_ctx2[(size_t)(i0 + row0 + 8) * 1024 + cu] =
          f2h2(o[2] * linv[mt * 2 + 1], o[3] * linv[mt * 2 + 1]);
    }
  }
}

// ======================= kernel 3: out (f16, BM=64, split-K 8) ===============
// grid (32, 8), 256 threads / 8 warps, warp grid 2m x 4n (32x32 tiles).
__global__ void __launch_bounds__(256) out_tc_kernel(const float* __restrict__ last) {
  extern __shared__ uint32_t smg[];
  uint32_t* Xs = smg;                 // 64 x GW
  uint32_t* Bt = smg + 64 * GW;       // 128 x GW

  const int m0 = blockIdx.x * 64;
  const int kc = blockIdx.y;
  const int tid = threadIdx.x;
  const int wid = tid >> 5;
  const int lane = tid & 31;
  const int qr = lane >> 2, qc = lane & 3;
  const int wm = (wid & 1) * 32;
  const int wn = (wid >> 1) * 32;

  float O[2][4][4];
#pragma unroll
  for (int mt = 0; mt < 2; mt++)
#pragma unroll
    for (int nt = 0; nt < 4; nt++)
#pragma unroll
      for (int e = 0; e < 4; e++) O[mt][nt][e] = 0.f;

  for (int ks2 = 0; ks2 < 2; ks2++) {
    const int kb = kc * 256 + ks2 * 128;
    __syncthreads();
    // X: direct uint4 copy of packed ctx (64 rows x 64 u32)
    for (int idx = tid; idx < 64 * 16; idx += 256) {
      int r = idx >> 4, c4 = (idx & 15) << 2;
      uint4 t = *reinterpret_cast<const uint4*>(
          g_ctx2 + (size_t)(m0 + r) * 1024 + (kb >> 1) + c4);
      *reinterpret_cast<uint4*>(Xs + r * GW + c4) = t;
    }
    // B^T: pack last[k][e] pairs along k
    for (int idx = tid; idx < 128 * 32; idx += 256) {
      int e = idx & 127, k4 = (idx >> 7) << 2;
      *reinterpret_cast<uint2*>(Bt + e * GW + (k4 >> 1)) = make_uint2(
          f2h2(last[(size_t)(kb + k4 + 0) * DIMD + e],
               last[(size_t)(kb + k4 + 1) * DIMD + e]),
          f2h2(last[(size_t)(kb + k4 + 2) * DIMD + e],
               last[(size_t)(kb + k4 + 3) * DIMD + e]));
    }
    __syncthreads();

#pragma unroll
    for (int ks = 0; ks < 8; ks++) {
      const int k8 = ks * 8;
      uint32_t Af[2][4];
#pragma unroll
      for (int mt = 0; mt < 2; mt++) {
        const uint32_t* ab = Xs + (wm + mt * 16 + qr) * GW + k8 + qc;
        Af[mt][0] = ab[0];
        Af[mt][1] = ab[8 * GW];
        Af[mt][2] = ab[4];
        Af[mt][3] = ab[8 * GW + 4];
      }
#pragma unroll
      for (int nt = 0; nt < 4; nt++) {
        const uint32_t* bb = Bt + (wn + nt * 8 + qr) * GW + k8 + qc;
        uint32_t b0 = bb[0], b1 = bb[4];
        mma_f16(O[0][nt], Af[0], b0, b1);
        mma_f16(O[1][nt], Af[1], b0, b1);
      }
    }
  }

  float* Pb = g_part + (size_t)kc * NSEQ * DIMD + (size_t)m0 * DIMD;
#pragma unroll
  for (int mt = 0; mt < 2; mt++) {
#pragma unroll
    for (int nt = 0; nt < 4; nt++) {
      const int row0 = wm + mt * 16 + qr;
      const int col = wn + nt * 8 + 2 * qc;
      const float* o = O[mt][nt];
      *reinterpret_cast<float2*>(Pb + (size_t)row0 * DIMD + col) = make_float2(o[0], o[1]);
      *reinterpret_cast<float2*>(Pb + (size_t)(row0 + 8) * DIMD + col) = make_float2(o[2], o[3]);
    }
  }
}

__global__ void __launch_bounds__(256) reduce_kernel(float* __restrict__ out) {
  int i = blockIdx.x * 256 + threadIdx.x;
  const float4* p = reinterpret_cast<const float4*>(g_part);
  float4 a = p[i];
#pragma unroll
  for (int kc = 1; kc < KSPLIT; kc++) {
    float4 b = p[(size_t)kc * (NSEQ * DIMD / 4) + i];
    a.x += b.x; a.y += b.y; a.z += b.z; a.w += b.w;
  }
  reinterpret_cast<float4*>(out)[i] = a;
}

// =====================================================================
extern "C" void kernel_launch(void* const* d_in, const int* in_sizes, int n_in,
                              void* d_out, int out_size) {
  int mi = -1;
  for (int i = 0; i < n_in; i++)
    if (in_sizes[i] == NSEQ * NSEQ) { mi = i; break; }
  if (mi < 0) mi = 3;

  const void* p[7];
  int np = 0;
  for (int i = 0; i < n_in && np < 7; i++) {
    if (i == mi) continue;
    p[np++] = d_in[i];
  }
  const float* q = (const float*)p[0];
  const float* k = (const float*)p[1];
  const float* v = (const float*)p[2];
  const float* Qw = (const float*)p[3];
  const float* Kw = (const float*)p[4];
  const float* Vw = (const float*)p[5];
  const float* last = (const float*)p[6];
  const int* mask = (const int*)d_in[mi];
  float* out = (float*)d_out;

  const int GEMM_SMEM = 2 * 128 * GW * 4;        // 69,632 B (proj)
  const int OUT_SMEM = (64 + 128) * GW * 4;      // 52,224 B (out)

  cudaFuncSetAttribute(proj_tc_kernel, cudaFuncAttributeMaxDynamicSharedMemorySize, GEMM_SMEM);
  cudaFuncSetAttribute(out_tc_kernel, cudaFuncAttributeMaxDynamicSharedMemorySize, OUT_SMEM);
  cudaFuncSetAttribute(attn_mma_kernel, cudaFuncAttributeMaxDynamicSharedMemorySize,
                       ATTN_SMEM_BYTES);

  proj_tc_kernel<<<dim3(NSEQ / 128, HEADS, 4), 256, GEMM_SMEM>>>(q, k, v, Qw, Kw, Vw, mask);
  attn_mma_kernel<<<dim3(NSEQ / 128, HEADS), 512, ATTN_SMEM_BYTES>>>();
  out_tc_kernel<<<dim3(NSEQ / 64, KSPLIT), 256, OUT_SMEM>>>(last);
  reduce_kernel<<<NSEQ * DIMD / 4 / 256, 256>>>(out);
}

// round 15
// speedup vs baseline: 1.4103x; 1.4103x over previous
#include <cuda_runtime.h>
#include <cstdint>

#define HEADS 16
#define DIMD 128
#define NSEQ 2048
/* exp(x*INV_SQRT_N) == exp2(x*C2) */
#define C2 0.0318793576f
#define KSPLIT 8

// ---------------- scratch (static device globals; no allocations) ----------------
__device__ __align__(16) uint32_t g_qp2[HEADS * NSEQ * 64];   // f16x2 packed
__device__ __align__(16) uint32_t g_kp2[HEADS * NSEQ * 64];   // f16x2 packed
__device__ __align__(16) uint32_t g_vp2[HEADS * NSEQ * 64];   // f16x2 packed
__device__ __align__(16) uint32_t g_ctx2[NSEQ * 1024];        // f16x2 packed [n][h*64+du]
__device__ __align__(16) float g_part[KSPLIT * NSEQ * DIMD];
__device__ __align__(16) unsigned g_mbits[(NSEQ / 32) * NSEQ];  // [word][row]

// ---------------- helpers ----------------
__device__ __forceinline__ uint32_t f2h2(float lo, float hi) {
  uint32_t r;
  asm("cvt.rn.f16x2.f32 %0, %1, %2;" : "=r"(r) : "f"(hi), "f"(lo));
  return r;
}
__device__ __forceinline__ uint32_t smem_u32(const void* p) {
  uint32_t a;
  asm("{ .reg .u64 t; cvta.to.shared.u64 t, %1; cvt.u32.u64 %0, t; }" : "=r"(a) : "l"(p));
  return a;
}

#define CP_ASYNC16(saddr, gptr)                                                 \
  asm volatile("cp.async.cg.shared.global [%0], [%1], 16;" ::"r"(saddr),        \
               "l"(gptr) : "memory")
#define CP_COMMIT() asm volatile("cp.async.commit_group;" ::: "memory")
#define CP_WAIT1() asm volatile("cp.async.wait_group 1;" ::: "memory")
#define CP_WAIT0() asm volatile("cp.async.wait_group 0;" ::: "memory")

__device__ __forceinline__ void mma_f16(float c[4], const uint32_t a[4],
                                        uint32_t b0, uint32_t b1) {
  asm volatile(
      "mma.sync.aligned.m16n8k16.row.col.f32.f16.f16.f32 "
      "{%0,%1,%2,%3}, {%4,%5,%6,%7}, {%8,%9}, {%0,%1,%2,%3};"
      : "+f"(c[0]), "+f"(c[1]), "+f"(c[2]), "+f"(c[3])
      : "r"(a[0]), "r"(a[1]), "r"(a[2]), "r"(a[3]), "r"(b0), "r"(b1));
}

__device__ __forceinline__ void ldmatrix_x4_trans(uint32_t& r0, uint32_t& r1,
                                                  uint32_t& r2, uint32_t& r3,
                                                  uint32_t addr) {
  asm volatile(
      "ldmatrix.sync.aligned.m8n8.x4.trans.shared.b16 {%0,%1,%2,%3}, [%4];"
      : "=r"(r0), "=r"(r1), "=r"(r2), "=r"(r3)
      : "r"(addr));
}

// ======================= kernel 1: projections (f16) + mask pack (z=3) ======
#define GW 68
__global__ void __launch_bounds__(256) proj_tc_kernel(
    const float* __restrict__ q, const float* __restrict__ k,
    const float* __restrict__ v, const float* __restrict__ Qw,
    const float* __restrict__ Kw, const float* __restrict__ Vw,
    const int* __restrict__ mask) {
  const int which = blockIdx.z;
  const int tid = threadIdx.x;
  const int wid = tid >> 5;
  const int lane = tid & 31;

  if (which == 3) {
    const int blkid = blockIdx.y * 16 + blockIdx.x;
    int wbase = blkid * 512 + wid * 64;
#pragma unroll 4
    for (int i = 0; i < 64; i++) {
      int w = wbase + i;
      int m = mask[(size_t)w * 32 + lane];
      unsigned bits = __ballot_sync(0xffffffffu, m != 0);
      if (lane == 0) g_mbits[(size_t)(w & 63) * NSEQ + (w >> 6)] = bits;
    }
    return;
  }

  extern __shared__ uint32_t smg[];
  uint32_t* Xs = smg;
  uint32_t* Ws = smg + 128 * GW;

  const float* A = (which == 0) ? q : (which == 1) ? k : v;
  const float* W = (which == 0) ? Qw : (which == 1) ? Kw : Vw;
  const int h = blockIdx.y;
  const int n0 = blockIdx.x * 128;
  const int qr = lane >> 2, qc = lane & 3;
  const int wm = (wid & 3) * 32;
  const int wn = (wid >> 2) * 64;

  for (int idx = tid; idx < 128 * 32; idx += 256) {
    int r = idx >> 5, c4 = (idx & 31) << 2;
    float4 t = *reinterpret_cast<const float4*>(A + (size_t)(n0 + r) * DIMD + c4);
    *reinterpret_cast<uint2*>(Xs + r * GW + (c4 >> 1)) =
        make_uint2(f2h2(t.x, t.y), f2h2(t.z, t.w));
  }
  const float* Wh = W + (size_t)h * DIMD * DIMD;
  for (int idx = tid; idx < 128 * 32; idx += 256) {
    int e = idx & 127, d4 = (idx >> 7) << 2;
    *reinterpret_cast<uint2*>(Ws + e * GW + (d4 >> 1)) = make_uint2(
        f2h2(Wh[(size_t)(d4 + 0) * DIMD + e], Wh[(size_t)(d4 + 1) * DIMD + e]),
        f2h2(Wh[(size_t)(d4 + 2) * DIMD + e], Wh[(size_t)(d4 + 3) * DIMD + e]));
  }
  __syncthreads();

  float O[2][8][4];
#pragma unroll
  for (int mt = 0; mt < 2; mt++)
#pragma unroll
    for (int nt = 0; nt < 8; nt++)
#pragma unroll
      for (int e = 0; e < 4; e++) O[mt][nt][e] = 0.f;

#pragma unroll
  for (int ks = 0; ks < 8; ks++) {
    const int k8 = ks * 8;
    uint32_t Af[2][4];
#pragma unroll
    for (int mt = 0; mt < 2; mt++) {
      const uint32_t* ab = Xs + (wm + mt * 16 + qr) * GW + k8 + qc;
      Af[mt][0] = ab[0];
      Af[mt][1] = ab[8 * GW];
      Af[mt][2] = ab[4];
      Af[mt][3] = ab[8 * GW + 4];
    }
#pragma unroll
    for (int nt = 0; nt < 8; nt++) {
      const uint32_t* bb = Ws + (wn + nt * 8 + qr) * GW + k8 + qc;
      uint32_t b0 = bb[0], b1 = bb[4];
      mma_f16(O[0][nt], Af[0], b0, b1);
      mma_f16(O[1][nt], Af[1], b0, b1);
    }
  }

  uint32_t* Cb2 = (which == 0 ? g_qp2 : which == 1 ? g_kp2 : g_vp2) +
                  ((size_t)h * NSEQ + n0) * 64;
#pragma unroll
  for (int mt = 0; mt < 2; mt++) {
#pragma unroll
    for (int nt = 0; nt < 8; nt++) {
      const int row0 = wm + mt * 16 + qr;
      const int cu = (wn + nt * 8) / 2 + qc;
      const float* o = O[mt][nt];
      Cb2[(size_t)row0 * 64 + cu] = f2h2(o[0], o[1]);
      Cb2[(size_t)(row0 + 8) * 64 + cu] = f2h2(o[2], o[3]);
    }
  }
}

// ======================= kernel 2: attention BM=128, cp.async double-buffer ==
// (verified R13 configuration: 211 KB smem, 1 block/SM, 512 threads)
#define ATW 68
#define AT_Q0 8704
#define AT_Q1 17408
#define AT_V0 26112
#define AT_V1 34816
#define AT_PP 43520
#define AT_L 52224
#define ATTN_SMEM_BYTES ((52224 + 512) * 4)

__global__ void __launch_bounds__(512) attn_mma_kernel() {
  extern __shared__ uint32_t smu[];
  const uint32_t sbase = smem_u32(smu);
  uint32_t* Ks2 = smu;
  uint32_t* Ps2 = smu + AT_PP;
  float* l_sh = reinterpret_cast<float*>(smu + AT_L);

  const int tid = threadIdx.x;
  const int wid = tid >> 5;
  const int lane = tid & 31;
  const int qr = lane >> 2;
  const int qc = lane & 3;
  const int wm = (wid & 3) * 32;
  const int wn = (wid >> 2) * 32;

  const int h = blockIdx.y;
  const int i0 = blockIdx.x * 128;

  const uint32_t* kp2 = g_kp2 + (size_t)h * NSEQ * 64;
  const uint32_t* qp2 = g_qp2 + (size_t)h * NSEQ * 64;
  const uint32_t* vp2 = g_vp2 + (size_t)h * NSEQ * 64;

  const int cr = tid >> 4;
  const int cc4 = (tid & 15) << 2;

  // K tile (persistent)
#pragma unroll
  for (int p = 0; p < 4; p++) {
    int r = cr + p * 32;
    uint4 t = *reinterpret_cast<const uint4*>(kp2 + (size_t)(i0 + r) * 64 + cc4);
    *reinterpret_cast<uint4*>(Ks2 + r * ATW + cc4) = t;
  }

  // prologue: cp.async tile 0 into buffer 0
#pragma unroll
  for (int p = 0; p < 4; p++) {
    int r = cr + p * 32;
    uint32_t so = (uint32_t)(r * ATW + cc4) * 4u;
    CP_ASYNC16(sbase + AT_Q0 * 4u + so, qp2 + (size_t)r * 64 + cc4);
    CP_ASYNC16(sbase + AT_V0 * 4u + so, vp2 + (size_t)r * 64 + cc4);
  }
  CP_COMMIT();

  const int lg = lane >> 3;
  const int vrow0 = (lane & 7) + ((lg & 1) << 3);
  const int vn0 = (wn >> 1) + ((lg >> 1) << 2);

  float O[2][4][4];
#pragma unroll
  for (int mt = 0; mt < 2; mt++)
#pragma unroll
    for (int nt = 0; nt < 4; nt++)
#pragma unroll
      for (int e = 0; e < 4; e++) O[mt][nt][e] = 0.f;
  float L[4] = {0.f, 0.f, 0.f, 0.f};

  const int row_rel[4] = {qr, qr + 8, qr + 16, qr + 24};

  for (int jt = 0; jt < NSEQ / 128; jt++) {
    const int j0 = jt * 128;
    __syncthreads();  // (A) prev PV done -> next buffer & P free

    if (jt < NSEQ / 128 - 1) {
      const int jn = j0 + 128;
      const uint32_t qoff = ((jt + 1) & 1) ? AT_Q1 : AT_Q0;
      const uint32_t voff = ((jt + 1) & 1) ? AT_V1 : AT_V0;
#pragma unroll
      for (int p = 0; p < 4; p++) {
        int r = cr + p * 32;
        uint32_t so = (uint32_t)(r * ATW + cc4) * 4u;
        CP_ASYNC16(sbase + qoff * 4u + so, qp2 + (size_t)(jn + r) * 64 + cc4);
        CP_ASYNC16(sbase + voff * 4u + so, vp2 + (size_t)(jn + r) * 64 + cc4);
      }
      CP_COMMIT();
      CP_WAIT1();
    } else {
      CP_WAIT0();
    }
    __syncthreads();  // (B) tile jt resident

    const uint32_t* Qs2 = smu + ((jt & 1) ? AT_Q1 : AT_Q0);
    const uint32_t vbase = sbase + ((jt & 1) ? AT_V1 : AT_V0) * 4u;

    // ---- S = K · Q^T
    float S[2][4][4];
#pragma unroll
    for (int mt = 0; mt < 2; mt++)
#pragma unroll
      for (int nt = 0; nt < 4; nt++)
#pragma unroll
        for (int e = 0; e < 4; e++) S[mt][nt][e] = 0.f;

#pragma unroll
    for (int ks = 0; ks < 8; ks++) {
      const int k8 = ks * 8;
      uint32_t A[2][4];
#pragma unroll
      for (int mt = 0; mt < 2; mt++) {
        const uint32_t* ab = Ks2 + (wm + mt * 16 + qr) * ATW + k8 + qc;
        A[mt][0] = ab[0];
        A[mt][1] = ab[8 * ATW];
        A[mt][2] = ab[4];
        A[mt][3] = ab[8 * ATW + 4];
      }
#pragma unroll
      for (int nt = 0; nt < 4; nt++) {
        const uint32_t* bb = Qs2 + (wn + nt * 8 + qr) * ATW + k8 + qc;
        uint32_t b0 = bb[0], b1 = bb[4];
        mma_f16(S[0][nt], A[0], b0, b1);
        mma_f16(S[1][nt], A[1], b0, b1);
      }
    }

    // ---- masked exp
    const unsigned* mb = g_mbits + (size_t)((j0 + wn) >> 5) * NSEQ + i0 + wm;
    unsigned mw[4];
#pragma unroll
    for (int r = 0; r < 4; r++) mw[r] = mb[row_rel[r]];

    float lacc[4] = {0.f, 0.f, 0.f, 0.f};
#pragma unroll
    for (int mt = 0; mt < 2; mt++) {
#pragma unroll
      for (int nt = 0; nt < 4; nt++) {
        const int b0 = nt * 8 + 2 * qc;
        const unsigned w0 = mw[mt * 2], w1 = mw[mt * 2 + 1];
        float* s = S[mt][nt];
        float p0 = ((w0 >> b0) & 1u) ? exp2f(s[0] * C2) : 0.f;
        float p1 = ((w0 >> (b0 + 1)) & 1u) ? exp2f(s[1] * C2) : 0.f;
        float p2 = ((w1 >> b0) & 1u) ? exp2f(s[2] * C2) : 0.f;
        float p3 = ((w1 >> (b0 + 1)) & 1u) ? exp2f(s[3] * C2) : 0.f;
        s[0] = p0; s[1] = p1; s[2] = p2; s[3] = p3;
        lacc[mt * 2] += p0 + p1;
        lacc[mt * 2 + 1] += p2 + p3;
      }
    }
#pragma unroll
    for (int r = 0; r < 4; r++) {
      float v = lacc[r];
      v += __shfl_xor_sync(0xffffffffu, v, 1);
      v += __shfl_xor_sync(0xffffffffu, v, 2);
      L[r] += v;
    }

    // ---- P -> smem as f16x2
#pragma unroll
    for (int mt = 0; mt < 2; mt++) {
#pragma unroll
      for (int nt = 0; nt < 4; nt++) {
        const int row0 = wm + mt * 16 + qr;
        const int cu = (wn >> 1) + nt * 4 + qc;
        const float* s = S[mt][nt];
        Ps2[row0 * ATW + cu] = f2h2(s[0], s[1]);
        Ps2[(row0 + 8) * ATW + cu] = f2h2(s[2], s[3]);
      }
    }
    __syncthreads();  // (C) P complete

    // ---- O += P · V
    uint32_t vaddr0 = vbase + (uint32_t)(vrow0 * ATW + vn0) * 4u;
    uint32_t vaddr1 = vaddr0 + 32u;
#pragma unroll
    for (int ks = 0; ks < 8; ks++) {
      const int k8 = ks * 8;
      uint32_t A[2][4];
#pragma unroll
      for (int mt = 0; mt < 2; mt++) {
        const uint32_t* ab = Ps2 + (wm + mt * 16 + qr) * ATW + k8 + qc;
        A[mt][0] = ab[0];
        A[mt][1] = ab[8 * ATW];
        A[mt][2] = ab[4];
        A[mt][3] = ab[8 * ATW + 4];
      }
      uint32_t b0, b1, b2, b3;
      ldmatrix_x4_trans(b0, b1, b2, b3, vaddr0);
      mma_f16(O[0][0], A[0], b0, b1);
      mma_f16(O[1][0], A[1], b0, b1);
      mma_f16(O[0][1], A[0], b2, b3);
      mma_f16(O[1][1], A[1], b2, b3);
      ldmatrix_x4_trans(b0, b1, b2, b3, vaddr1);
      mma_f16(O[0][2], A[0], b0, b1);
      mma_f16(O[1][2], A[1], b0, b1);
      mma_f16(O[0][3], A[0], b2, b3);
      mma_f16(O[1][3], A[1], b2, b3);
      vaddr0 += 16u * ATW * 4u;
      vaddr1 += 16u * ATW * 4u;
    }
  }

  // combine row sums
  if (qc == 0) {
#pragma unroll
    for (int r = 0; r < 4; r++)
      l_sh[(wid >> 2) * 128 + wm + row_rel[r]] = L[r];
  }
  __syncthreads();
  float linv[4];
#pragma unroll
  for (int r = 0; r < 4; r++) {
    int row = wm + row_rel[r];
    linv[r] = 1.f / (l_sh[row] + l_sh[128 + row] + l_sh[256 + row] + l_sh[384 + row]);
  }

  // epilogue: write ctx as packed f16x2
#pragma unroll
  for (int mt = 0; mt < 2; mt++) {
#pragma unroll
    for (int nt = 0; nt < 4; nt++) {
      const int row0 = wm + mt * 16 + qr;
      const int cu = h * 64 + (wn >> 1) + nt * 4 + qc;
      const float* o = O[mt][nt];
      g_ctx2[(size_t)(i0 + row0) * 1024 + cu] =
          f2h2(o[0] * linv[mt * 2], o[1] * linv[mt * 2]);
      g_ctx2[(size_t)(i0 + row0 + 8) * 1024 + cu] =
          f2h2(o[2] * linv[mt * 2 + 1], o[3] * linv[mt * 2 + 1]);
    }
  }
}

// ======================= kernel 3: out (f16, BM=64, split-K 8) ===============
__global__ void __launch_bounds__(256) out_tc_kernel(const float* __restrict__ last) {
  extern __shared__ uint32_t smg[];
  uint32_t* Xs = smg;                 // 64 x GW
  uint32_t* Bt = smg + 64 * GW;       // 128 x GW

  const int m0 = blockIdx.x * 64;
  const int kc = blockIdx.y;
  const int tid = threadIdx.x;
  const int wid = tid >> 5;
  const int lane = tid & 31;
  const int qr = lane >> 2, qc = lane & 3;
  const int wm = (wid & 1) * 32;
  const int wn = (wid >> 1) * 32;

  float O[2][4][4];
#pragma unroll
  for (int mt = 0; mt < 2; mt++)
#pragma unroll
    for (int nt = 0; nt < 4; nt++)
#pragma unroll
      for (int e = 0; e < 4; e++) O[mt][nt][e] = 0.f;

  for (int ks2 = 0; ks2 < 2; ks2++) {
    const int kb = kc * 256 + ks2 * 128;
    __syncthreads();
    for (int idx = tid; idx < 64 * 16; idx += 256) {
      int r = idx >> 4, c4 = (idx & 15) << 2;
      uint4 t = *reinterpret_cast<const uint4*>(
          g_ctx2 + (size_t)(m0 + r) * 1024 + (kb >> 1) + c4);
      *reinterpret_cast<uint4*>(Xs + r * GW + c4) = t;
    }
    for (int idx = tid; idx < 128 * 32; idx += 256) {
      int e = idx & 127, k4 = (idx >> 7) << 2;
      *reinterpret_cast<uint2*>(Bt + e * GW + (k4 >> 1)) = make_uint2(
          f2h2(last[(size_t)(kb + k4 + 0) * DIMD + e],
               last[(size_t)(kb + k4 + 1) * DIMD + e]),
          f2h2(last[(size_t)(kb + k4 + 2) * DIMD + e],
               last[(size_t)(kb + k4 + 3) * DIMD + e]));
    }
    __syncthreads();

#pragma unroll
    for (int ks = 0; ks < 8; ks++) {
      const int k8 = ks * 8;
      uint32_t Af[2][4];
#pragma unroll
      for (int mt = 0; mt < 2; mt++) {
        const uint32_t* ab = Xs + (wm + mt * 16 + qr) * GW + k8 + qc;
        Af[mt][0] = ab[0];
        Af[mt][1] = ab[8 * GW];
        Af[mt][2] = ab[4];
        Af[mt][3] = ab[8 * GW + 4];
      }
#pragma unroll
      for (int nt = 0; nt < 4; nt++) {
        const uint32_t* bb = Bt + (wn + nt * 8 + qr) * GW + k8 + qc;
        uint32_t b0 = bb[0], b1 = bb[4];
        mma_f16(O[0][nt], Af[0], b0, b1);
        mma_f16(O[1][nt], Af[1], b0, b1);
      }
    }
  }

  float* Pb = g_part + (size_t)kc * NSEQ * DIMD + (size_t)m0 * DIMD;
#pragma unroll
  for (int mt = 0; mt < 2; mt++) {
#pragma unroll
    for (int nt = 0; nt < 4; nt++) {
      const int row0 = wm + mt * 16 + qr;
      const int col = wn + nt * 8 + 2 * qc;
      const float* o = O[mt][nt];
      *reinterpret_cast<float2*>(Pb + (size_t)row0 * DIMD + col) = make_float2(o[0], o[1]);
      *reinterpret_cast<float2*>(Pb + (size_t)(row0 + 8) * DIMD + col) = make_float2(o[2], o[3]);
    }
  }
}

__global__ void __launch_bounds__(256) reduce_kernel(float* __restrict__ out) {
  int i = blockIdx.x * 256 + threadIdx.x;
  const float4* p = reinterpret_cast<const float4*>(g_part);
  float4 a = p[i];
#pragma unroll
  for (int kc = 1; kc < KSPLIT; kc++) {
    float4 b = p[(size_t)kc * (NSEQ * DIMD / 4) + i];
    a.x += b.x; a.y += b.y; a.z += b.z; a.w += b.w;
  }
  reinterpret_cast<float4*>(out)[i] = a;
}

// =====================================================================
extern "C" void kernel_launch(void* const* d_in, const int* in_sizes, int n_in,
                              void* d_out, int out_size) {
  int mi = -1;
  for (int i = 0; i < n_in; i++)
    if (in_sizes[i] == NSEQ * NSEQ) { mi = i; break; }
  if (mi < 0) mi = 3;

  const void* p[7];
  int np = 0;
  for (int i = 0; i < n_in && np < 7; i++) {
    if (i == mi) continue;
    p[np++] = d_in[i];
  }
  const float* q = (const float*)p[0];
  const float* k = (const float*)p[1];
  const float* v = (const float*)p[2];
  const float* Qw = (const float*)p[3];
  const float* Kw = (const float*)p[4];
  const float* Vw = (const float*)p[5];
  const float* last = (const float*)p[6];
  const int* mask = (const int*)d_in[mi];
  float* out = (float*)d_out;

  const int GEMM_SMEM = 2 * 128 * GW * 4;        // 69,632 B (proj)
  const int OUT_SMEM = (64 + 128) * GW * 4;      // 52,224 B (out)

  cudaFuncSetAttribute(proj_tc_kernel, cudaFuncAttributeMaxDynamicSharedMemorySize, GEMM_SMEM);
  cudaFuncSetAttribute(out_tc_kernel, cudaFuncAttributeMaxDynamicSharedMemorySize, OUT_SMEM);
  cudaFuncSetAttribute(attn_mma_kernel, cudaFuncAttributeMaxDynamicSharedMemorySize,
                       ATTN_SMEM_BYTES);

  proj_tc_kernel<<<dim3(NSEQ / 128, HEADS, 4), 256, GEMM_SMEM>>>(q, k, v, Qw, Kw, Vw, mask);
  attn_mma_kernel<<<dim3(NSEQ / 128, HEADS), 512, ATTN_SMEM_BYTES>>>();
  out_tc_kernel<<<dim3(NSEQ / 64, KSPLIT), 256, OUT_SMEM>>>(last);
  reduce_kernel<<<NSEQ * DIMD / 4 / 256, 256>>>(out);
}

// round 16
// speedup vs baseline: 1.4615x; 1.0363x over previous
#include <cuda_runtime.h>
#include <cstdint>

#define HEADS 16
#define DIMD 128
#define NSEQ 2048
/* exp(x*INV_SQRT_N) == exp2(x*C2) */
#define C2 0.0318793576f
#define KSPLIT 8

// ---------------- scratch (static device globals; no allocations) ----------------
__device__ __align__(16) uint32_t g_qp2[HEADS * NSEQ * 64];   // f16x2 packed
__device__ __align__(16) uint32_t g_kp2[HEADS * NSEQ * 64];   // f16x2 packed
__device__ __align__(16) uint32_t g_vp2[HEADS * NSEQ * 64];   // f16x2 packed
__device__ __align__(16) uint32_t g_ctx2[NSEQ * 1024];        // f16x2 packed [n][h*64+du]
__device__ __align__(16) float g_part[KSPLIT * NSEQ * DIMD];
__device__ __align__(16) unsigned g_mbits[(NSEQ / 32) * NSEQ];  // [word][row]

// ---------------- helpers ----------------
__device__ __forceinline__ uint32_t f2h2(float lo, float hi) {
  uint32_t r;
  asm("cvt.rn.f16x2.f32 %0, %1, %2;" : "=r"(r) : "f"(hi), "f"(lo));
  return r;
}
__device__ __forceinline__ uint32_t smem_u32(const void* p) {
  uint32_t a;
  asm("{ .reg .u64 t; cvta.to.shared.u64 t, %1; cvt.u32.u64 %0, t; }" : "=r"(a) : "l"(p));
  return a;
}

#define CP_ASYNC16(saddr, gptr)                                                 \
  asm volatile("cp.async.cg.shared.global [%0], [%1], 16;" ::"r"(saddr),        \
               "l"(gptr) : "memory")
#define CP_COMMIT() asm volatile("cp.async.commit_group;" ::: "memory")
#define CP_WAIT0() asm volatile("cp.async.wait_group 0;" ::: "memory")

__device__ __forceinline__ void mma_f16(float c[4], const uint32_t a[4],
                                        uint32_t b0, uint32_t b1) {
  asm volatile(
      "mma.sync.aligned.m16n8k16.row.col.f32.f16.f16.f32 "
      "{%0,%1,%2,%3}, {%4,%5,%6,%7}, {%8,%9}, {%0,%1,%2,%3};"
      : "+f"(c[0]), "+f"(c[1]), "+f"(c[2]), "+f"(c[3])
      : "r"(a[0]), "r"(a[1]), "r"(a[2]), "r"(a[3]), "r"(b0), "r"(b1));
}

__device__ __forceinline__ void ldmatrix_x4_trans(uint32_t& r0, uint32_t& r1,
                                                  uint32_t& r2, uint32_t& r3,
                                                  uint32_t addr) {
  asm volatile(
      "ldmatrix.sync.aligned.m8n8.x4.trans.shared.b16 {%0,%1,%2,%3}, [%4];"
      : "=r"(r0), "=r"(r1), "=r"(r2), "=r"(r3)
      : "r"(addr));
}

// ======================= kernel 1: projections (f16, 4 heads/block) =========
// grid (16 n-tiles, 4 head-groups, 4): z=0/1/2 q/k/v; z=3 mask packing.
#define GW 68
__global__ void __launch_bounds__(256) proj_tc_kernel(
    const float* __restrict__ q, const float* __restrict__ k,
    const float* __restrict__ v, const float* __restrict__ Qw,
    const float* __restrict__ Kw, const float* __restrict__ Vw,
    const int* __restrict__ mask) {
  const int which = blockIdx.z;
  const int tid = threadIdx.x;
  const int wid = tid >> 5;
  const int lane = tid & 31;

  if (which == 3) {
    // mask packing: 64 blocks x 8 warps x 256 words (transposed bit layout)
    const int blkid = blockIdx.y * 16 + blockIdx.x;  // 0..63
    int wbase = blkid * 2048 + wid * 256;
#pragma unroll 4
    for (int i = 0; i < 256; i++) {
      int w = wbase + i;
      int m = mask[(size_t)w * 32 + lane];
      unsigned bits = __ballot_sync(0xffffffffu, m != 0);
      if (lane == 0) g_mbits[(size_t)(w & 63) * NSEQ + (w >> 6)] = bits;
    }
    return;
  }

  extern __shared__ uint32_t smg[];
  uint32_t* Xs = smg;
  uint32_t* Ws = smg + 128 * GW;

  const float* A = (which == 0) ? q : (which == 1) ? k : v;
  const float* W = (which == 0) ? Qw : (which == 1) ? Kw : Vw;
  uint32_t* Cbase = (which == 0) ? g_qp2 : (which == 1) ? g_kp2 : g_vp2;
  const int n0 = blockIdx.x * 128;
  const int hbase = blockIdx.y * 4;
  const int qr = lane >> 2, qc = lane & 3;
  const int wm = (wid & 3) * 32;
  const int wn = (wid >> 2) * 64;

  // X packed f16 (once per block; head-invariant)
  for (int idx = tid; idx < 128 * 32; idx += 256) {
    int r = idx >> 5, c4 = (idx & 31) << 2;
    float4 t = *reinterpret_cast<const float4*>(A + (size_t)(n0 + r) * DIMD + c4);
    *reinterpret_cast<uint2*>(Xs + r * GW + (c4 >> 1)) =
        make_uint2(f2h2(t.x, t.y), f2h2(t.z, t.w));
  }

  for (int hh = 0; hh < 4; hh++) {
    const int h = hbase + hh;
    // W^T packed f16 (coalesced along e)
    const float* Wh = W + (size_t)h * DIMD * DIMD;
    for (int idx = tid; idx < 128 * 32; idx += 256) {
      int e = idx & 127, d4 = (idx >> 7) << 2;
      *reinterpret_cast<uint2*>(Ws + e * GW + (d4 >> 1)) = make_uint2(
          f2h2(Wh[(size_t)(d4 + 0) * DIMD + e], Wh[(size_t)(d4 + 1) * DIMD + e]),
          f2h2(Wh[(size_t)(d4 + 2) * DIMD + e], Wh[(size_t)(d4 + 3) * DIMD + e]));
    }
    __syncthreads();  // X (first iter) + Ws ready

    float O[2][8][4];
#pragma unroll
    for (int mt = 0; mt < 2; mt++)
#pragma unroll
      for (int nt = 0; nt < 8; nt++)
#pragma unroll
        for (int e = 0; e < 4; e++) O[mt][nt][e] = 0.f;

#pragma unroll
    for (int ks = 0; ks < 8; ks++) {
      const int k8 = ks * 8;
      uint32_t Af[2][4];
#pragma unroll
      for (int mt = 0; mt < 2; mt++) {
        const uint32_t* ab = Xs + (wm + mt * 16 + qr) * GW + k8 + qc;
        Af[mt][0] = ab[0];
        Af[mt][1] = ab[8 * GW];
        Af[mt][2] = ab[4];
        Af[mt][3] = ab[8 * GW + 4];
      }
#pragma unroll
      for (int nt = 0; nt < 8; nt++) {
        const uint32_t* bb = Ws + (wn + nt * 8 + qr) * GW + k8 + qc;
        uint32_t b0 = bb[0], b1 = bb[4];
        mma_f16(O[0][nt], Af[0], b0, b1);
        mma_f16(O[1][nt], Af[1], b0, b1);
      }
    }

    uint32_t* Cb2 = Cbase + ((size_t)h * NSEQ + n0) * 64;
#pragma unroll
    for (int mt = 0; mt < 2; mt++) {
#pragma unroll
      for (int nt = 0; nt < 8; nt++) {
        const int row0 = wm + mt * 16 + qr;
        const int cu = (wn + nt * 8) / 2 + qc;
        const float* o = O[mt][nt];
        Cb2[(size_t)row0 * 64 + cu] = f2h2(o[0], o[1]);
        Cb2[(size_t)(row0 + 8) * 64 + cu] = f2h2(o[2], o[3]);
      }
    }
    __syncthreads();  // all warps done reading Ws before next head's fill
  }
}

// ======================= kernel 2: attention BM=128, cp.async double-buffer ==
// R13 configuration with sync(A) removed: 2 syncs/tile. Next tile's copies are
// issued after sync B (all warps provably past PV of jt-1).
#define ATW 68
#define AT_Q0 8704
#define AT_Q1 17408
#define AT_V0 26112
#define AT_V1 34816
#define AT_PP 43520
#define AT_L 52224
#define ATTN_SMEM_BYTES ((52224 + 512) * 4)

__global__ void __launch_bounds__(512) attn_mma_kernel() {
  extern __shared__ uint32_t smu[];
  const uint32_t sbase = smem_u32(smu);
  uint32_t* Ks2 = smu;
  uint32_t* Ps2 = smu + AT_PP;
  float* l_sh = reinterpret_cast<float*>(smu + AT_L);

  const int tid = threadIdx.x;
  const int wid = tid >> 5;
  const int lane = tid & 31;
  const int qr = lane >> 2;
  const int qc = lane & 3;
  const int wm = (wid & 3) * 32;
  const int wn = (wid >> 2) * 32;

  const int h = blockIdx.y;
  const int i0 = blockIdx.x * 128;

  const uint32_t* kp2 = g_kp2 + (size_t)h * NSEQ * 64;
  const uint32_t* qp2 = g_qp2 + (size_t)h * NSEQ * 64;
  const uint32_t* vp2 = g_vp2 + (size_t)h * NSEQ * 64;

  const int cr = tid >> 4;
  const int cc4 = (tid & 15) << 2;

  // K tile (persistent)
#pragma unroll
  for (int p = 0; p < 4; p++) {
    int r = cr + p * 32;
    uint4 t = *reinterpret_cast<const uint4*>(kp2 + (size_t)(i0 + r) * 64 + cc4);
    *reinterpret_cast<uint4*>(Ks2 + r * ATW + cc4) = t;
  }

  // prologue: cp.async tile 0 into buffer 0
#pragma unroll
  for (int p = 0; p < 4; p++) {
    int r = cr + p * 32;
    uint32_t so = (uint32_t)(r * ATW + cc4) * 4u;
    CP_ASYNC16(sbase + AT_Q0 * 4u + so, qp2 + (size_t)r * 64 + cc4);
    CP_ASYNC16(sbase + AT_V0 * 4u + so, vp2 + (size_t)r * 64 + cc4);
  }
  CP_COMMIT();

  const int lg = lane >> 3;
  const int vrow0 = (lane & 7) + ((lg & 1) << 3);
  const int vn0 = (wn >> 1) + ((lg >> 1) << 2);

  float O[2][4][4];
#pragma unroll
  for (int mt = 0; mt < 2; mt++)
#pragma unroll
    for (int nt = 0; nt < 4; nt++)
#pragma unroll
      for (int e = 0; e < 4; e++) O[mt][nt][e] = 0.f;
  float L[4] = {0.f, 0.f, 0.f, 0.f};

  const int row_rel[4] = {qr, qr + 8, qr + 16, qr + 24};

  for (int jt = 0; jt < NSEQ / 128; jt++) {
    const int j0 = jt * 128;

    CP_WAIT0();       // tile jt's copies (this thread's) complete
    __syncthreads();  // (B) all threads' copies complete & visible; PV(jt-1) done

    // issue tile jt+1 into the other buffer (overwrites jt-1's buffer: safe)
    if (jt < NSEQ / 128 - 1) {
      const int jn = j0 + 128;
      const uint32_t qoff = ((jt + 1) & 1) ? AT_Q1 : AT_Q0;
      const uint32_t voff = ((jt + 1) & 1) ? AT_V1 : AT_V0;
#pragma unroll
      for (int p = 0; p < 4; p++) {
        int r = cr + p * 32;
        uint32_t so = (uint32_t)(r * ATW + cc4) * 4u;
        CP_ASYNC16(sbase + qoff * 4u + so, qp2 + (size_t)(jn + r) * 64 + cc4);
        CP_ASYNC16(sbase + voff * 4u + so, vp2 + (size_t)(jn + r) * 64 + cc4);
      }
      CP_COMMIT();
    }

    const uint32_t* Qs2 = smu + ((jt & 1) ? AT_Q1 : AT_Q0);
    const uint32_t vbase = sbase + ((jt & 1) ? AT_V1 : AT_V0) * 4u;

    // ---- S = K · Q^T
    float S[2][4][4];
#pragma unroll
    for (int mt = 0; mt < 2; mt++)
#pragma unroll
      for (int nt = 0; nt < 4; nt++)
#pragma unroll
        for (int e = 0; e < 4; e++) S[mt][nt][e] = 0.f;

#pragma unroll
    for (int ks = 0; ks < 8; ks++) {
      const int k8 = ks * 8;
      uint32_t A[2][4];
#pragma unroll
      for (int mt = 0; mt < 2; mt++) {
        const uint32_t* ab = Ks2 + (wm + mt * 16 + qr) * ATW + k8 + qc;
        A[mt][0] = ab[0];
        A[mt][1] = ab[8 * ATW];
        A[mt][2] = ab[4];
        A[mt][3] = ab[8 * ATW + 4];
      }
#pragma unroll
      for (int nt = 0; nt < 4; nt++) {
        const uint32_t* bb = Qs2 + (wn + nt * 8 + qr) * ATW + k8 + qc;
        uint32_t b0 = bb[0], b1 = bb[4];
        mma_f16(S[0][nt], A[0], b0, b1);
        mma_f16(S[1][nt], A[1], b0, b1);
      }
    }

    // ---- masked exp
    const unsigned* mb = g_mbits + (size_t)((j0 + wn) >> 5) * NSEQ + i0 + wm;
    unsigned mw[4];
#pragma unroll
    for (int r = 0; r < 4; r++) mw[r] = mb[row_rel[r]];

    float lacc[4] = {0.f, 0.f, 0.f, 0.f};
#pragma unroll
    for (int mt = 0; mt < 2; mt++) {
#pragma unroll
      for (int nt = 0; nt < 4; nt++) {
        const int b0 = nt * 8 + 2 * qc;
        const unsigned w0 = mw[mt * 2], w1 = mw[mt * 2 + 1];
        float* s = S[mt][nt];
        float p0 = ((w0 >> b0) & 1u) ? exp2f(s[0] * C2) : 0.f;
        float p1 = ((w0 >> (b0 + 1)) & 1u) ? exp2f(s[1] * C2) : 0.f;
        float p2 = ((w1 >> b0) & 1u) ? exp2f(s[2] * C2) : 0.f;
        float p3 = ((w1 >> (b0 + 1)) & 1u) ? exp2f(s[3] * C2) : 0.f;
        s[0] = p0; s[1] = p1; s[2] = p2; s[3] = p3;
        lacc[mt * 2] += p0 + p1;
        lacc[mt * 2 + 1] += p2 + p3;
      }
    }
#pragma unroll
    for (int r = 0; r < 4; r++) {
      float v = lacc[r];
      v += __shfl_xor_sync(0xffffffffu, v, 1);
      v += __shfl_xor_sync(0xffffffffu, v, 2);
      L[r] += v;
    }

    // ---- P -> smem as f16x2 (own buffer)
#pragma unroll
    for (int mt = 0; mt < 2; mt++) {
#pragma unroll
      for (int nt = 0; nt < 4; nt++) {
        const int row0 = wm + mt * 16 + qr;
        const int cu = (wn >> 1) + nt * 4 + qc;
        const float* s = S[mt][nt];
        Ps2[row0 * ATW + cu] = f2h2(s[0], s[1]);
        Ps2[(row0 + 8) * ATW + cu] = f2h2(s[2], s[3]);
      }
    }
    __syncthreads();  // (C) P complete

    // ---- O += P · V
    uint32_t vaddr0 = vbase + (uint32_t)(vrow0 * ATW + vn0) * 4u;
    uint32_t vaddr1 = vaddr0 + 32u;
#pragma unroll
    for (int ks = 0; ks < 8; ks++) {
      const int k8 = ks * 8;
      uint32_t A[2][4];
#pragma unroll
      for (int mt = 0; mt < 2; mt++) {
        const uint32_t* ab = Ps2 + (wm + mt * 16 + qr) * ATW + k8 + qc;
        A[mt][0] = ab[0];
        A[mt][1] = ab[8 * ATW];
        A[mt][2] = ab[4];
        A[mt][3] = ab[8 * ATW + 4];
      }
      uint32_t b0, b1, b2, b3;
      ldmatrix_x4_trans(b0, b1, b2, b3, vaddr0);
      mma_f16(O[0][0], A[0], b0, b1);
      mma_f16(O[1][0], A[1], b0, b1);
      mma_f16(O[0][1], A[0], b2, b3);
      mma_f16(O[1][1], A[1], b2, b3);
      ldmatrix_x4_trans(b0, b1, b2, b3, vaddr1);
      mma_f16(O[0][2], A[0], b0, b1);
      mma_f16(O[1][2], A[1], b0, b1);
      mma_f16(O[0][3], A[0], b2, b3);
      mma_f16(O[1][3], A[1], b2, b3);
      vaddr0 += 16u * ATW * 4u;
      vaddr1 += 16u * ATW * 4u;
    }
  }

  // combine row sums
  if (qc == 0) {
#pragma unroll
    for (int r = 0; r < 4; r++)
      l_sh[(wid >> 2) * 128 + wm + row_rel[r]] = L[r];
  }
  __syncthreads();
  float linv[4];
#pragma unroll
  for (int r = 0; r < 4; r++) {
    int row = wm + row_rel[r];
    linv[r] = 1.f / (l_sh[row] + l_sh[128 + row] + l_sh[256 + row] + l_sh[384 + row]);
  }

  // epilogue: write ctx as packed f16x2
#pragma unroll
  for (int mt = 0; mt < 2; mt++) {
#pragma unroll
    for (int nt = 0; nt < 4; nt++) {
      const int row0 = wm + mt * 16 + qr;
      const int cu = h * 64 + (wn >> 1) + nt * 4 + qc;
      const float* o = O[mt][nt];
      g_ctx2[(size_t)(i0 + row0) * 1024 + cu] =
          f2h2(o[0] * linv[mt * 2], o[1] * linv[mt * 2]);
      g_ctx2[(size_t)(i0 + row0 + 8) * 1024 + cu] =
          f2h2(o[2] * linv[mt * 2 + 1], o[3] * linv[mt * 2 + 1]);
    }
  }
}

// ======================= kernel 3: out (f16, BM=64, split-K 8) ===============
__global__ void __launch_bounds__(256) out_tc_kernel(const float* __restrict__ last) {
  extern __shared__ uint32_t smg[];
  uint32_t* Xs = smg;                 // 64 x GW
  uint32_t* Bt = smg + 64 * GW;       // 128 x GW

  const int m0 = blockIdx.x * 64;
  const int kc = blockIdx.y;
  const int tid = threadIdx.x;
  const int wid = tid >> 5;
  const int lane = tid & 31;
  const int qr = lane >> 2, qc = lane & 3;
  const int wm = (wid & 1) * 32;
  const int wn = (wid >> 1) * 32;

  float O[2][4][4];
#pragma unroll
  for (int mt = 0; mt < 2; mt++)
#pragma unroll
    for (int nt = 0; nt < 4; nt++)
#pragma unroll
      for (int e = 0; e < 4; e++) O[mt][nt][e] = 0.f;

  for (int ks2 = 0; ks2 < 2; ks2++) {
    const int kb = kc * 256 + ks2 * 128;
    __syncthreads();
    for (int idx = tid; idx < 64 * 16; idx += 256) {
      int r = idx >> 4, c4 = (idx & 15) << 2;
      uint4 t = *reinterpret_cast<const uint4*>(
          g_ctx2 + (size_t)(m0 + r) * 1024 + (kb >> 1) + c4);
      *reinterpret_cast<uint4*>(Xs + r * GW + c4) = t;
    }
    for (int idx = tid; idx < 128 * 32; idx += 256) {
      int e = idx & 127, k4 = (idx >> 7) << 2;
      *reinterpret_cast<uint2*>(Bt + e * GW + (k4 >> 1)) = make_uint2(
          f2h2(last[(size_t)(kb + k4 + 0) * DIMD + e],
               last[(size_t)(kb + k4 + 1) * DIMD + e]),
          f2h2(last[(size_t)(kb + k4 + 2) * DIMD + e],
               last[(size_t)(kb + k4 + 3) * DIMD + e]));
    }
    __syncthreads();

#pragma unroll
    for (int ks = 0; ks < 8; ks++) {
      const int k8 = ks * 8;
      uint32_t Af[2][4];
#pragma unroll
      for (int mt = 0; mt < 2; mt++) {
        const uint32_t* ab = Xs + (wm + mt * 16 + qr) * GW + k8 + qc;
        Af[mt][0] = ab[0];
        Af[mt][1] = ab[8 * GW];
        Af[mt][2] = ab[4];
        Af[mt][3] = ab[8 * GW + 4];
      }
#pragma unroll
      for (int nt = 0; nt < 4; nt++) {
        const uint32_t* bb = Bt + (wn + nt * 8 + qr) * GW + k8 + qc;
        uint32_t b0 = bb[0], b1 = bb[4];
        mma_f16(O[0][nt], Af[0], b0, b1);
        mma_f16(O[1][nt], Af[1], b0, b1);
      }
    }
  }

  float* Pb = g_part + (size_t)kc * NSEQ * DIMD + (size_t)m0 * DIMD;
#pragma unroll
  for (int mt = 0; mt < 2; mt++) {
#pragma unroll
    for (int nt = 0; nt < 4; nt++) {
      const int row0 = wm + mt * 16 + qr;
      const int col = wn + nt * 8 + 2 * qc;
      const float* o = O[mt][nt];
      *reinterpret_cast<float2*>(Pb + (size_t)row0 * DIMD + col) = make_float2(o[0], o[1]);
      *reinterpret_cast<float2*>(Pb + (size_t)(row0 + 8) * DIMD + col) = make_float2(o[2], o[3]);
    }
  }
}

__global__ void __launch_bounds__(256) reduce_kernel(float* __restrict__ out) {
  int i = blockIdx.x * 256 + threadIdx.x;
  const float4* p = reinterpret_cast<const float4*>(g_part);
  float4 a = p[i];
#pragma unroll
  for (int kc = 1; kc < KSPLIT; kc++) {
    float4 b = p[(size_t)kc * (NSEQ * DIMD / 4) + i];
    a.x += b.x; a.y += b.y; a.z += b.z; a.w += b.w;
  }
  reinterpret_cast<float4*>(out)[i] = a;
}

// =====================================================================
extern "C" void kernel_launch(void* const* d_in, const int* in_sizes, int n_in,
                              void* d_out, int out_size) {
  int mi = -1;
  for (int i = 0; i < n_in; i++)
    if (in_sizes[i] == NSEQ * NSEQ) { mi = i; break; }
  if (mi < 0) mi = 3;

  const void* p[7];
  int np = 0;
  for (int i = 0; i < n_in && np < 7; i++) {
    if (i == mi) continue;
    p[np++] = d_in[i];
  }
  const float* q = (const float*)p[0];
  const float* k = (const float*)p[1];
  const float* v = (const float*)p[2];
  const float* Qw = (const float*)p[3];
  const float* Kw = (const float*)p[4];
  const float* Vw = (const float*)p[5];
  const float* last = (const float*)p[6];
  const int* mask = (const int*)d_in[mi];
  float* out = (float*)d_out;

  const int GEMM_SMEM = 2 * 128 * GW * 4;        // 69,632 B (proj)
  const int OUT_SMEM = (64 + 128) * GW * 4;      // 52,224 B (out)

  cudaFuncSetAttribute(proj_tc_kernel, cudaFuncAttributeMaxDynamicSharedMemorySize, GEMM_SMEM);
  cudaFuncSetAttribute(out_tc_kernel, cudaFuncAttributeMaxDynamicSharedMemorySize, OUT_SMEM);
  cudaFuncSetAttribute(attn_mma_kernel, cudaFuncAttributeMaxDynamicSharedMemorySize,
                       ATTN_SMEM_BYTES);

  proj_tc_kernel<<<dim3(16, 4, 4), 256, GEMM_SMEM>>>(q, k, v, Qw, Kw, Vw, mask);
  attn_mma_kernel<<<dim3(NSEQ / 128, HEADS), 512, ATTN_SMEM_BYTES>>>();
  out_tc_kernel<<<dim3(NSEQ / 64, KSPLIT), 256, OUT_SMEM>>>(last);
  reduce_kernel<<<NSEQ * DIMD / 4 / 256, 256>>>(out);
}